// round 10
// baseline (speedup 1.0000x reference)
#include <cuda_runtime.h>

#define HH 4096
#define WW 1024
#define SS 16
#define NSEG 17
#define NCHB 8            // partials per column = one per 512-row block
#define NR32 128          // 32-row groups (k_part granularity)
#define WIN 20.0f
#define FINF 3.0e38f

// ---- scratch (__device__ globals; no allocation allowed) -------------------
__device__ float g_p32[NR32 * WW];        // per-32-row-group column sums
__device__ float g_mag[WW];               // per-column total mass
__device__ float g_cum[HH * WW];          // 16MB normalized cumsum
// hard partials, dense layout [bh][s][w] (coalesced writes), 1.7MB total
__device__ float g_hB[NCHB * NSEG * WW];
__device__ float g_hA[NCHB * NSEG * WW];
__device__ float g_hC[NCHB * NSEG * WW];
__device__ float g_w0[SS * WW], g_w1[SS * WW], g_w2[SS * WW];  // window sums
__device__ float g_sum, g_cnt;
__device__ unsigned g_ticket;

// data-independent per-segment reference (MUST be bit-identical in k_main/k_cols)
__device__ __forceinline__ float seg_ref(float sL, float sR) {
    return (sL + sR) * (0.5f / (float)HH);
}

// ---------------------------------------------------------------------------
// Kernel A: 32-row-group column sums. warp = group, lane = column. MLP=32.
// Also resets the scalar accumulators for this replay.
// ---------------------------------------------------------------------------
__global__ void __launch_bounds__(256) k_part(const float* __restrict__ preds) {
    if (blockIdx.x == 0 && blockIdx.y == 0 && threadIdx.x == 0) {
        g_sum = 0.f; g_cnt = 0.f; g_ticket = 0u;
    }
    const int v = threadIdx.x >> 5, lane = threadIdx.x & 31;
    const int col = blockIdx.x * 32 + lane;
    const int gi = blockIdx.y * 8 + v;            // 0..127
    const float* p = preds + (size_t)gi * 32 * WW + col;
    float a0 = 0.f, a1 = 0.f, a2 = 0.f, a3 = 0.f;
#pragma unroll
    for (int r = 0; r < 32; r += 4) {
        a0 += p[(size_t)(r + 0) * WW];
        a1 += p[(size_t)(r + 1) * WW];
        a2 += p[(size_t)(r + 2) * WW];
        a3 += p[(size_t)(r + 3) * WW];
    }
    g_p32[gi * WW + col] = (a0 + a1) + (a2 + a3);
}

// ---------------------------------------------------------------------------
// Kernel B: main sweep. warp = 64-row chunk, lane = column. Batched loads
// (MLP=16), running normalized cumsum -> g_cum, hard moments about the
// snake-derived per-segment ref, merged across the block's 8 chunks via
// rare smem atomics, written densely + coalesced. NO sigmoids here.
// ---------------------------------------------------------------------------
__global__ void __launch_bounds__(256) k_main(const float* __restrict__ preds,
                                              const float* __restrict__ snakes) {
    __shared__ float s_p[NR32][32];   // 16KB: group sums for this col-group
    __shared__ float snk[SS][32];
    __shared__ float accB[NSEG][32], accA[NSEG][32], accC[NSEG][32];

    const int bw = blockIdx.x, bh = blockIdx.y;
    const int tid = threadIdx.x;
    const int v = tid >> 5, lane = tid & 31;
    const int col = bw * 32 + lane;

    for (int e = tid; e < NR32 * 32; e += 256)
        s_p[e >> 5][e & 31] = g_p32[(e >> 5) * WW + bw * 32 + (e & 31)];
    for (int e = tid; e < SS * 32; e += 256)
        snk[e >> 5][e & 31] = snakes[(e >> 5) * WW + bw * 32 + (e & 31)];
    for (int e = tid; e < NSEG * 32; e += 256) {
        accB[e >> 5][e & 31] = 0.f;
        accA[e >> 5][e & 31] = 0.f;
        accC[e >> 5][e & 31] = 0.f;
    }
    __syncthreads();

    const int gi = bh * 8 + v;        // 64-row chunk id, 0..63
    const int h0 = gi * 64;
    const int gpre = gi * 2;          // 32-row groups before this chunk

    float base = 0.f;
#pragma unroll 8
    for (int i = 0; i < gpre; i++) base += s_p[i][lane];
    float mag = base;
#pragma unroll 8
    for (int i = gpre; i < NR32; i++) mag += s_p[i][lane];
    const float inv = 1.0f / mag;
    if (gi == 0) g_mag[col] = mag;

    const float* p = preds + (size_t)h0 * WW + col;
    float* outc = g_cum + (size_t)h0 * WW + col;

    int j = 0;
    while (j < SS && snk[j][lane] <= (float)h0) j++;
    float sR = (j < SS) ? snk[j][lane] : (float)HH;
    float ref = seg_ref((j > 0) ? snk[j - 1][lane] : 0.f, sR);
    float sNext = (j < SS) ? sR : FINF;

    float cum = base;
    float A = 0.f, C = 0.f, B = 0.f;

#pragma unroll
    for (int b = 0; b < 4; b++) {
        float regs[16];
#pragma unroll
        for (int k = 0; k < 16; k++)                       // independent loads
            regs[k] = p[(size_t)(b * 16 + k) * WW];
#pragma unroll
        for (int k = 0; k < 16; k++) {
            const int r = b * 16 + k;
            cum += regs[k];
            const float x = cum * inv;
            outc[(size_t)r * WW] = x;
            const float hf = (float)(h0 + r);
            if (hf >= sNext) {                             // segment crossed
                if (B > 0.f) {
                    atomicAdd(&accB[j][lane], B);
                    atomicAdd(&accA[j][lane], A);
                    atomicAdd(&accC[j][lane], C);
                }
                A = C = B = 0.f;
                j++;
                while (j < SS && snk[j][lane] <= hf) j++;
                sR = (j < SS) ? snk[j][lane] : (float)HH;
                ref = seg_ref(snk[j - 1][lane], sR);
                sNext = (j < SS) ? sR : FINF;
            }
            float dx = x - ref;
            A += dx; C = fmaf(dx, dx, C); B += 1.f;
        }
    }
    if (B > 0.f) {
        atomicAdd(&accB[j][lane], B);
        atomicAdd(&accA[j][lane], A);
        atomicAdd(&accC[j][lane], C);
    }
    __syncthreads();

    // dense coalesced write: [bh][s][w]
    for (int e = tid; e < NSEG * 32; e += 256) {
        int s = e >> 5, l = e & 31;
        size_t o = ((size_t)bh * NSEG + s) * WW + bw * 32 + l;
        g_hB[o] = accB[s][l];
        g_hA[o] = accA[s][l];
        g_hC[o] = accC[s][l];
    }
}

// ---------------------------------------------------------------------------
// Kernel C: window corrections. warp = (boundary b, column w); <=41 rows.
// delta = sigmoid(s-h) - step(s-h); sums of (d, d*x, d*x^2).
// ---------------------------------------------------------------------------
__global__ void __launch_bounds__(256) k_win(const float* __restrict__ snakes) {
    const int u = blockIdx.x * 8 + (threadIdx.x >> 5);   // 0..16383
    const int lane = threadIdx.x & 31;
    const int b = u >> 10, w = u & (WW - 1);
    const float s = snakes[b * WW + w];
    const int lo = max(0, (int)ceilf(s - WIN));
    const int hi = min(HH, (int)floorf(s + WIN) + 1);
    const float* cw = g_cum + w;
    float d0 = 0.f, d1 = 0.f, d2 = 0.f;
    for (int h = lo + lane; h < hi; h += 32) {
        float t = s - (float)h;
        float e = __expf(-fabsf(t));
        float sg = e / (1.f + e);
        float dlt = (t > 0.f) ? -sg : sg;      // sigmoid - step, stable
        float x = cw[(size_t)h * WW];
        d0 += dlt; d1 += dlt * x; d2 = fmaf(dlt * x, x, d2);
    }
#pragma unroll
    for (int d = 16; d; d >>= 1) {
        d0 += __shfl_xor_sync(0xffffffffu, d0, d);
        d1 += __shfl_xor_sync(0xffffffffu, d1, d);
        d2 += __shfl_xor_sync(0xffffffffu, d2, d);
    }
    if (lane == 0) {
        g_w0[b * WW + w] = d0; g_w1[b * WW + w] = d1; g_w2[b * WW + w] = d2;
    }
}

// ---------------------------------------------------------------------------
// Kernel D: warp = (segment s, column w). Lanes 0..7 load the 8 block
// partials (plain sums — common ref), shuffle-merge, window corrections,
// masked accumulate, last-block finalize. Grid = 2176 blocks of 8 warps.
// ---------------------------------------------------------------------------
__global__ void __launch_bounds__(256) k_cols(const float* __restrict__ snakes,
                                              float* __restrict__ out) {
    const int wid = threadIdx.x >> 5, lane = threadIdx.x & 31;
    const int u = blockIdx.x * 8 + wid;       // 0..17407
    const int s = u >> 10;
    const int w = u & (WW - 1);

    float Bv = 0.f, Av = 0.f, Cv = 0.f;
    if (lane < NCHB) {
        size_t idx = ((size_t)lane * NSEG + s) * WW + w;
        Bv = g_hB[idx]; Av = g_hA[idx]; Cv = g_hC[idx];
    }
#pragma unroll
    for (int d = 16; d; d >>= 1) {
        Bv += __shfl_xor_sync(0xffffffffu, Bv, d);
        Av += __shfl_xor_sync(0xffffffffu, Av, d);
        Cv += __shfl_xor_sync(0xffffffffu, Cv, d);
    }

    __shared__ float rs[8], rc[8];
    __shared__ bool isLast;
    if (lane == 0) {
        float sL = (s > 0)  ? snakes[(s - 1) * WW + w] : 0.f;
        float sR = (s < SS) ? snakes[s * WW + w]       : (float)HH;
        float ref = seg_ref(sL, sR);

        float B = Bv, mean = ref, M2 = 0.f;
        if (B > 0.f) { mean = ref + Av / B; M2 = Cv - Av * Av / B; }

        float D0 = 0.f, D1 = 0.f, D2 = 0.f;
        if (s < SS) { D0 += g_w0[s * WW + w]; D1 += g_w1[s * WW + w]; D2 += g_w2[s * WW + w]; }
        if (s > 0)  { int b = s - 1;
                      D0 -= g_w0[b * WW + w]; D1 -= g_w1[b * WW + w]; D2 -= g_w2[b * WW + w]; }

        float d1c = D1 - mean * D0;
        float d2c = D2 - 2.f * mean * D1 + mean * mean * D0;
        float Bt = B + D0;
        float V = (Bt > 1e-12f) ? (M2 + d2c) - d1c * d1c / Bt : 0.f;

        bool mask = g_mag[w] > 1.0f;
        rs[wid] = mask ? V : 0.f;
        rc[wid] = (s == 0 && mask) ? 1.f : 0.f;
    }
    __syncthreads();
    if (threadIdx.x == 0) {
        float S_ = 0.f, C_ = 0.f;
#pragma unroll
        for (int k = 0; k < 8; k++) { S_ += rs[k]; C_ += rc[k]; }
        atomicAdd(&g_sum, S_);
        atomicAdd(&g_cnt, C_);
        __threadfence();
        unsigned t = atomicAdd(&g_ticket, 1u);
        isLast = (t == gridDim.x - 1);
    }
    __syncthreads();
    if (isLast && threadIdx.x == 0)
        out[0] = g_sum / ((float)(NSEG * HH)) / g_cnt;
}

// ---------------------------------------------------------------------------
extern "C" void kernel_launch(void* const* d_in, const int* in_sizes, int n_in,
                              void* d_out, int out_size) {
    const float* snakes = (const float*)d_in[0];   // [16, 1024]
    const float* preds  = (const float*)d_in[1];   // [4096, 1024]
    (void)in_sizes; (void)n_in; (void)out_size;

    k_part<<<dim3(WW / 32, 16), 256>>>(preds);
    k_main<<<dim3(WW / 32, 8), 256>>>(preds, snakes);
    k_win<<<(SS * WW) / 8, 256>>>(snakes);
    k_cols<<<(NSEG * WW) / 8, 256>>>(snakes, (float*)d_out);  // warp per (s,w)
}

// round 11
// speedup vs baseline: 1.1372x; 1.1372x over previous
#include <cuda_runtime.h>

#define HH 4096
#define WW 1024
#define SS 16
#define NSEG 17
#define NCHB 8            // row-blocks per column (512 rows each)
#define WIN 20.0f
#define FINF 3.0e38f

// ---- scratch (__device__ globals; zero-initialized, no allocation) ---------
__device__ float g_bsum[NCHB * WW];       // per-(row-block, column) sums
__device__ unsigned g_flag[(WW / 32) * NCHB];  // [bw*8+bh] publish flags
__device__ float g_mag[WW];               // per-column total mass
__device__ float g_cum[HH * WW];          // 16MB normalized cumsum
// hard partials, dense layout [bh][s][w]
__device__ float g_hB[NCHB * NSEG * WW];
__device__ float g_hA[NCHB * NSEG * WW];
__device__ float g_hC[NCHB * NSEG * WW];
__device__ float g_sum, g_cnt;
__device__ unsigned g_ticket;

// data-independent per-segment reference (bit-identical in both kernels)
__device__ __forceinline__ float seg_ref(float sL, float sR) {
    return (sL + sR) * (0.5f / (float)HH);
}

// ---------------------------------------------------------------------------
// K1: fused partial-sums + main sweep. Block (bw,bh) = 32 cols x 512 rows,
// warp v = 64-row chunk, lane = column. Pass 1 computes block-column sums,
// publishes them, spins for the column group's 8 blocks, then scans.
// All 256 blocks are co-resident (launch_bounds minBlocks=2 over 148 SMs).
// ---------------------------------------------------------------------------
__global__ void __launch_bounds__(256, 2) k_sweep(const float* __restrict__ preds,
                                                  const float* __restrict__ snakes) {
    __shared__ float s_chunk[8][32];  // per-chunk column sums within block
    __shared__ float snk[SS][32];
    __shared__ float accB[NSEG][32], accA[NSEG][32], accC[NSEG][32];

    const int bw = blockIdx.x, bh = blockIdx.y;
    const int tid = threadIdx.x;
    const int v = tid >> 5, lane = tid & 31;
    const int col = bw * 32 + lane;

    if (bw == 0 && bh == 0 && tid == 0) { g_sum = 0.f; g_cnt = 0.f; g_ticket = 0u; }

    for (int e = tid; e < SS * 32; e += 256)
        snk[e >> 5][e & 31] = snakes[(e >> 5) * WW + bw * 32 + (e & 31)];
    for (int e = tid; e < NSEG * 32; e += 256) {
        accB[e >> 5][e & 31] = 0.f;
        accA[e >> 5][e & 31] = 0.f;
        accC[e >> 5][e & 31] = 0.f;
    }

    const int h0 = (bh * 8 + v) * 64;
    const float* p = preds + (size_t)h0 * WW + col;

    // ---- pass 1: chunk sum (4 batches of 16 independent loads) ----
    float csum = 0.f;
#pragma unroll
    for (int b = 0; b < 4; b++) {
        float r0 = 0.f, r1 = 0.f, r2 = 0.f, r3 = 0.f;
#pragma unroll
        for (int k = 0; k < 16; k += 4) {
            r0 += p[(size_t)(b * 16 + k + 0) * WW];
            r1 += p[(size_t)(b * 16 + k + 1) * WW];
            r2 += p[(size_t)(b * 16 + k + 2) * WW];
            r3 += p[(size_t)(b * 16 + k + 3) * WW];
        }
        csum += (r0 + r1) + (r2 + r3);
    }
    s_chunk[v][lane] = csum;
    __syncthreads();

    // ---- publish block-column sums, release flag ----
    if (tid < 32) {
        float bsum = 0.f;
#pragma unroll
        for (int v2 = 0; v2 < 8; v2++) bsum += s_chunk[v2][tid];
        g_bsum[bh * WW + bw * 32 + tid] = bsum;
    }
    __syncthreads();
    if (tid == 0) {
        __threadfence();
        atomicExch(&g_flag[bw * NCHB + bh], 1u);
    }

    // ---- spin for all 8 row-blocks of this column group ----
    if (tid < NCHB) {
        volatile unsigned* f = &g_flag[bw * NCHB + tid];
        while (*f == 0u) __nanosleep(20);
        __threadfence();   // acquire
    }
    __syncthreads();

    // ---- base / mag ----
    float base = 0.f, mag = 0.f;
#pragma unroll
    for (int i = 0; i < NCHB; i++) {
        float bs = g_bsum[i * WW + col];
        base += (i < bh) ? bs : 0.f;
        mag += bs;
    }
#pragma unroll
    for (int v2 = 0; v2 < 8; v2++)
        base += (v2 < v) ? s_chunk[v2][lane] : 0.f;
    const float inv = 1.0f / mag;
    if (bh == 0 && tid < 32) g_mag[col] = mag;

    // ---- pass 2: scan + hard moments about snake-derived ref ----
    float* outc = g_cum + (size_t)h0 * WW + col;

    int j = 0;
    while (j < SS && snk[j][lane] <= (float)h0) j++;
    float sR = (j < SS) ? snk[j][lane] : (float)HH;
    float ref = seg_ref((j > 0) ? snk[j - 1][lane] : 0.f, sR);
    float sNext = (j < SS) ? sR : FINF;

    float cum = base;
    float A = 0.f, C = 0.f, B = 0.f;

#pragma unroll
    for (int b = 0; b < 4; b++) {
        float regs[16];
#pragma unroll
        for (int k = 0; k < 16; k++)
            regs[k] = p[(size_t)(b * 16 + k) * WW];
#pragma unroll
        for (int k = 0; k < 16; k++) {
            const int r = b * 16 + k;
            cum += regs[k];
            const float x = cum * inv;
            outc[(size_t)r * WW] = x;
            const float hf = (float)(h0 + r);
            if (hf >= sNext) {                       // segment crossed
                if (B > 0.f) {
                    atomicAdd(&accB[j][lane], B);
                    atomicAdd(&accA[j][lane], A);
                    atomicAdd(&accC[j][lane], C);
                }
                A = C = B = 0.f;
                j++;
                while (j < SS && snk[j][lane] <= hf) j++;
                sR = (j < SS) ? snk[j][lane] : (float)HH;
                ref = seg_ref(snk[j - 1][lane], sR);
                sNext = (j < SS) ? sR : FINF;
            }
            float dx = x - ref;
            A += dx; C = fmaf(dx, dx, C); B += 1.f;
        }
    }
    if (B > 0.f) {
        atomicAdd(&accB[j][lane], B);
        atomicAdd(&accA[j][lane], A);
        atomicAdd(&accC[j][lane], C);
    }
    __syncthreads();

    // dense coalesced partial write: [bh][s][w]
    for (int e = tid; e < NSEG * 32; e += 256) {
        int s = e >> 5, l = e & 31;
        size_t o = ((size_t)bh * NSEG + s) * WW + bw * 32 + l;
        g_hB[o] = accB[s][l];
        g_hA[o] = accA[s][l];
        g_hC[o] = accC[s][l];
    }
}

// ---------------------------------------------------------------------------
// K2: fused window corrections + combine + reduce. Warp per (segment s,
// column w). The warp computes sigmoid-window sums for boundaries s and s-1
// directly from g_cum (<=41 rows each), merges the 8 dense hard partials,
// recenters, masks, accumulates, finalizes. Also resets K1's flags.
// ---------------------------------------------------------------------------
__global__ void __launch_bounds__(256) k_fin(const float* __restrict__ snakes,
                                             float* __restrict__ out) {
    const int wid = threadIdx.x >> 5, lane = threadIdx.x & 31;
    const int u = blockIdx.x * 8 + wid;       // 0..17407
    const int s = u >> 10;
    const int w = u & (WW - 1);

    if (blockIdx.x == 0) g_flag[threadIdx.x] = 0u;   // reset for next replay

    // hard partials (lanes 0..7), plain sums — common ref
    float Bv = 0.f, Av = 0.f, Cv = 0.f;
    if (lane < NCHB) {
        size_t idx = ((size_t)lane * NSEG + s) * WW + w;
        Bv = g_hB[idx]; Av = g_hA[idx]; Cv = g_hC[idx];
    }

    // window corrections: +boundary s, -boundary s-1 (raw x moments)
    float D0 = 0.f, D1 = 0.f, D2 = 0.f;
    if (s < SS) {
        float sp = snakes[s * WW + w];
        int lo = max(0, (int)ceilf(sp - WIN));
        int hi = min(HH, (int)floorf(sp + WIN) + 1);
        for (int h = lo + lane; h < hi; h += 32) {
            float t = sp - (float)h;
            float e = __expf(-fabsf(t));
            float sg = e / (1.f + e);
            float dlt = (t > 0.f) ? -sg : sg;   // sigmoid - step
            float x = g_cum[(size_t)h * WW + w];
            D0 += dlt; D1 += dlt * x; D2 = fmaf(dlt * x, x, D2);
        }
    }
    if (s > 0) {
        float sp = snakes[(s - 1) * WW + w];
        int lo = max(0, (int)ceilf(sp - WIN));
        int hi = min(HH, (int)floorf(sp + WIN) + 1);
        for (int h = lo + lane; h < hi; h += 32) {
            float t = sp - (float)h;
            float e = __expf(-fabsf(t));
            float sg = e / (1.f + e);
            float dlt = (t > 0.f) ? -sg : sg;
            float x = g_cum[(size_t)h * WW + w];
            D0 -= dlt; D1 -= dlt * x; D2 = fmaf(-dlt * x, x, D2);
        }
    }

#pragma unroll
    for (int d = 16; d; d >>= 1) {
        Bv += __shfl_xor_sync(0xffffffffu, Bv, d);
        Av += __shfl_xor_sync(0xffffffffu, Av, d);
        Cv += __shfl_xor_sync(0xffffffffu, Cv, d);
        D0 += __shfl_xor_sync(0xffffffffu, D0, d);
        D1 += __shfl_xor_sync(0xffffffffu, D1, d);
        D2 += __shfl_xor_sync(0xffffffffu, D2, d);
    }

    __shared__ float rs[8], rc[8];
    __shared__ bool isLast;
    if (lane == 0) {
        float sL = (s > 0)  ? snakes[(s - 1) * WW + w] : 0.f;
        float sR = (s < SS) ? snakes[s * WW + w]       : (float)HH;
        float ref = seg_ref(sL, sR);

        float B = Bv, mean = ref, M2 = 0.f;
        if (B > 0.f) { mean = ref + Av / B; M2 = Cv - Av * Av / B; }

        float d1c = D1 - mean * D0;
        float d2c = D2 - 2.f * mean * D1 + mean * mean * D0;
        float Bt = B + D0;
        float V = (Bt > 1e-12f) ? (M2 + d2c) - d1c * d1c / Bt : 0.f;

        bool mask = g_mag[w] > 1.0f;
        rs[wid] = mask ? V : 0.f;
        rc[wid] = (s == 0 && mask) ? 1.f : 0.f;
    }
    __syncthreads();
    if (threadIdx.x == 0) {
        float S_ = 0.f, C_ = 0.f;
#pragma unroll
        for (int k = 0; k < 8; k++) { S_ += rs[k]; C_ += rc[k]; }
        atomicAdd(&g_sum, S_);
        atomicAdd(&g_cnt, C_);
        __threadfence();
        unsigned t = atomicAdd(&g_ticket, 1u);
        isLast = (t == gridDim.x - 1);
    }
    __syncthreads();
    if (isLast && threadIdx.x == 0)
        out[0] = g_sum / ((float)(NSEG * HH)) / g_cnt;
}

// ---------------------------------------------------------------------------
extern "C" void kernel_launch(void* const* d_in, const int* in_sizes, int n_in,
                              void* d_out, int out_size) {
    const float* snakes = (const float*)d_in[0];   // [16, 1024]
    const float* preds  = (const float*)d_in[1];   // [4096, 1024]
    (void)in_sizes; (void)n_in; (void)out_size;

    k_sweep<<<dim3(WW / 32, NCHB), 256>>>(preds, snakes);
    k_fin<<<(NSEG * WW) / 8, 256>>>(snakes, (float*)d_out);
}

// round 12
// speedup vs baseline: 1.3768x; 1.2107x over previous
#include <cuda_runtime.h>

#define HH 4096
#define WW 1024
#define SS 16
#define NSEG 17
#define NCHB 8            // row-blocks per column (512 rows each)
#define WIN 12.0f
#define FINF 3.0e38f

// ---- scratch (__device__ globals; zero-initialized, no allocation) ---------
__device__ float g_bsum[NCHB * WW];            // per-(row-block, column) sums
__device__ unsigned g_flag[(WW / 32) * NCHB];  // [bw*8+bh] publish flags
__device__ float g_mag[WW];                    // per-column total mass
__device__ float g_cum[HH * WW];               // 16MB normalized cumsum
// hard partials, dense layout [bh][s][w]
__device__ float g_hB[NCHB * NSEG * WW];
__device__ float g_hA[NCHB * NSEG * WW];
__device__ float g_hC[NCHB * NSEG * WW];
__device__ float g_sum, g_cnt;
__device__ unsigned g_ticket;

// data-independent per-segment reference (bit-identical in both kernels)
__device__ __forceinline__ float seg_ref(float sL, float sR) {
    return (sL + sR) * (0.5f / (float)HH);
}

// ---------------------------------------------------------------------------
// K1: fused partial-sums + main sweep. Block (bw,bh) = 32 cols x 512 rows,
// warp v = 64-row chunk, lane = column. Pass 1 computes block-column sums,
// publishes them, spins for the column group's 8 blocks, then scans.
// All 256 blocks are co-resident (launch_bounds minBlocks=2 over 148 SMs).
// ---------------------------------------------------------------------------
__global__ void __launch_bounds__(256, 2) k_sweep(const float* __restrict__ preds,
                                                  const float* __restrict__ snakes) {
    __shared__ float s_chunk[8][32];  // per-chunk column sums within block
    __shared__ float snk[SS][32];
    __shared__ float accB[NSEG][32], accA[NSEG][32], accC[NSEG][32];

    const int bw = blockIdx.x, bh = blockIdx.y;
    const int tid = threadIdx.x;
    const int v = tid >> 5, lane = tid & 31;
    const int col = bw * 32 + lane;

    if (bw == 0 && bh == 0 && tid == 0) { g_sum = 0.f; g_cnt = 0.f; g_ticket = 0u; }

    for (int e = tid; e < SS * 32; e += 256)
        snk[e >> 5][e & 31] = snakes[(e >> 5) * WW + bw * 32 + (e & 31)];
    for (int e = tid; e < NSEG * 32; e += 256) {
        accB[e >> 5][e & 31] = 0.f;
        accA[e >> 5][e & 31] = 0.f;
        accC[e >> 5][e & 31] = 0.f;
    }

    const int h0 = (bh * 8 + v) * 64;
    const float* p = preds + (size_t)h0 * WW + col;

    // ---- pass 1: chunk sum (4 batches of 16 independent loads) ----
    float csum = 0.f;
#pragma unroll
    for (int b = 0; b < 4; b++) {
        float r0 = 0.f, r1 = 0.f, r2 = 0.f, r3 = 0.f;
#pragma unroll
        for (int k = 0; k < 16; k += 4) {
            r0 += p[(size_t)(b * 16 + k + 0) * WW];
            r1 += p[(size_t)(b * 16 + k + 1) * WW];
            r2 += p[(size_t)(b * 16 + k + 2) * WW];
            r3 += p[(size_t)(b * 16 + k + 3) * WW];
        }
        csum += (r0 + r1) + (r2 + r3);
    }
    s_chunk[v][lane] = csum;
    __syncthreads();

    // ---- publish block-column sums, release flag ----
    if (tid < 32) {
        float bsum = 0.f;
#pragma unroll
        for (int v2 = 0; v2 < 8; v2++) bsum += s_chunk[v2][tid];
        g_bsum[bh * WW + bw * 32 + tid] = bsum;
    }
    __syncthreads();
    if (tid == 0) {
        __threadfence();
        atomicExch(&g_flag[bw * NCHB + bh], 1u);
    }

    // ---- spin for all 8 row-blocks of this column group ----
    if (tid < NCHB) {
        volatile unsigned* f = &g_flag[bw * NCHB + tid];
        while (*f == 0u) __nanosleep(20);
        __threadfence();   // acquire
    }
    __syncthreads();

    // ---- base / mag ----
    float base = 0.f, mag = 0.f;
#pragma unroll
    for (int i = 0; i < NCHB; i++) {
        float bs = g_bsum[i * WW + col];
        base += (i < bh) ? bs : 0.f;
        mag += bs;
    }
#pragma unroll
    for (int v2 = 0; v2 < 8; v2++)
        base += (v2 < v) ? s_chunk[v2][lane] : 0.f;
    const float inv = 1.0f / mag;
    if (bh == 0 && tid < 32) g_mag[col] = mag;

    // ---- pass 2: scan + hard moments about snake-derived ref ----
    float* outc = g_cum + (size_t)h0 * WW + col;

    int j = 0;
    while (j < SS && snk[j][lane] <= (float)h0) j++;
    float sR = (j < SS) ? snk[j][lane] : (float)HH;
    float ref = seg_ref((j > 0) ? snk[j - 1][lane] : 0.f, sR);
    float sNext = (j < SS) ? sR : FINF;

    float cum = base;
    float A = 0.f, C = 0.f, B = 0.f;

#pragma unroll
    for (int b = 0; b < 4; b++) {
        float regs[16];
#pragma unroll
        for (int k = 0; k < 16; k++)
            regs[k] = p[(size_t)(b * 16 + k) * WW];
#pragma unroll
        for (int k = 0; k < 16; k++) {
            const int r = b * 16 + k;
            cum += regs[k];
            const float x = cum * inv;
            outc[(size_t)r * WW] = x;
            const float hf = (float)(h0 + r);
            if (hf >= sNext) {                       // segment crossed
                if (B > 0.f) {
                    atomicAdd(&accB[j][lane], B);
                    atomicAdd(&accA[j][lane], A);
                    atomicAdd(&accC[j][lane], C);
                }
                A = C = B = 0.f;
                j++;
                while (j < SS && snk[j][lane] <= hf) j++;
                sR = (j < SS) ? snk[j][lane] : (float)HH;
                ref = seg_ref(snk[j - 1][lane], sR);
                sNext = (j < SS) ? sR : FINF;
            }
            float dx = x - ref;
            A += dx; C = fmaf(dx, dx, C); B += 1.f;
        }
    }
    if (B > 0.f) {
        atomicAdd(&accB[j][lane], B);
        atomicAdd(&accA[j][lane], A);
        atomicAdd(&accC[j][lane], C);
    }
    __syncthreads();

    // dense coalesced partial write: [bh][s][w]
    for (int e = tid; e < NSEG * 32; e += 256) {
        int s = e >> 5, l = e & 31;
        size_t o = ((size_t)bh * NSEG + s) * WW + bw * 32 + l;
        g_hB[o] = accB[s][l];
        g_hA[o] = accA[s][l];
        g_hC[o] = accC[s][l];
    }
}

// ---------------------------------------------------------------------------
// K2: block per column w. Phase 1: warp wid computes windows wid and wid+8
// once each (lane = row; no divergence, results in smem). Phase 2: threads
// 0..16 combine segments (24 MLP-friendly partial loads each). Warp 0
// reduces, masks, ticket-finalizes. Also resets K1's flags for next replay.
// ---------------------------------------------------------------------------
__global__ void __launch_bounds__(256) k_fin(const float* __restrict__ snakes,
                                             float* __restrict__ out) {
    __shared__ float s_snk[SS];
    __shared__ float sw0[SS], sw1[SS], sw2[SS];
    __shared__ float sV[32];

    const int w = blockIdx.x;
    const int tid = threadIdx.x;
    const int wid = tid >> 5, lane = tid & 31;

    if (w == 0) g_flag[tid] = 0u;     // 256 entries, reset for next replay
    if (tid < SS) s_snk[tid] = snakes[tid * WW + w];
    if (tid < 32) sV[tid] = 0.f;
    __syncthreads();

    // ---- phase 1: each warp computes 2 boundary windows (each ONCE) ----
#pragma unroll
    for (int bb = 0; bb < 2; bb++) {
        const int b = wid + bb * 8;
        const float sp = s_snk[b];
        const int lo = max(0, (int)ceilf(sp - WIN));
        const int hi = min(HH, (int)floorf(sp + WIN) + 1);
        float d0 = 0.f, d1 = 0.f, d2 = 0.f;
        for (int h = lo + lane; h < hi; h += 32) {
            float t = sp - (float)h;
            float e = __expf(-fabsf(t));
            float sg = e / (1.f + e);
            float dlt = (t > 0.f) ? -sg : sg;   // sigmoid - step, stable
            float x = g_cum[(size_t)h * WW + w];
            d0 += dlt; d1 += dlt * x; d2 = fmaf(dlt * x, x, d2);
        }
#pragma unroll
        for (int d = 16; d; d >>= 1) {
            d0 += __shfl_xor_sync(0xffffffffu, d0, d);
            d1 += __shfl_xor_sync(0xffffffffu, d1, d);
            d2 += __shfl_xor_sync(0xffffffffu, d2, d);
        }
        if (lane == 0) { sw0[b] = d0; sw1[b] = d1; sw2[b] = d2; }
    }
    __syncthreads();

    // ---- phase 2: per-segment combine (threads 0..16) ----
    if (tid < NSEG) {
        const int s = tid;
        float B = 0.f, A = 0.f, C = 0.f;
#pragma unroll
        for (int bh = 0; bh < NCHB; bh++) {
            size_t idx = ((size_t)bh * NSEG + s) * WW + w;
            B += g_hB[idx]; A += g_hA[idx]; C += g_hC[idx];
        }
        float sL = (s > 0)  ? s_snk[s - 1] : 0.f;
        float sR = (s < SS) ? s_snk[s]     : (float)HH;
        float ref = seg_ref(sL, sR);

        float mean = ref, M2 = 0.f;
        if (B > 0.f) { mean = ref + A / B; M2 = C - A * A / B; }

        float D0 = 0.f, D1 = 0.f, D2 = 0.f;
        if (s < SS) { D0 += sw0[s]; D1 += sw1[s]; D2 += sw2[s]; }
        if (s > 0)  { D0 -= sw0[s - 1]; D1 -= sw1[s - 1]; D2 -= sw2[s - 1]; }

        float d1c = D1 - mean * D0;
        float d2c = D2 - 2.f * mean * D1 + mean * mean * D0;
        float Bt = B + D0;
        sV[tid] = (Bt > 1e-12f) ? (M2 + d2c) - d1c * d1c / Bt : 0.f;
    }
    __syncthreads();

    // ---- reduce 17 values, mask, accumulate, finalize ----
    if (tid < 32) {
        float v = sV[tid];
#pragma unroll
        for (int d = 16; d; d >>= 1)
            v += __shfl_xor_sync(0xffffffffu, v, d);
        if (tid == 0) {
            bool mask = g_mag[w] > 1.0f;
            atomicAdd(&g_sum, mask ? v : 0.f);
            atomicAdd(&g_cnt, mask ? 1.f : 0.f);
            __threadfence();
            unsigned t = atomicAdd(&g_ticket, 1u);
            if (t == gridDim.x - 1)
                out[0] = g_sum / ((float)(NSEG * HH)) / g_cnt;
        }
    }
}

// ---------------------------------------------------------------------------
extern "C" void kernel_launch(void* const* d_in, const int* in_sizes, int n_in,
                              void* d_out, int out_size) {
    const float* snakes = (const float*)d_in[0];   // [16, 1024]
    const float* preds  = (const float*)d_in[1];   // [4096, 1024]
    (void)in_sizes; (void)n_in; (void)out_size;

    k_sweep<<<dim3(WW / 32, NCHB), 256>>>(preds, snakes);
    k_fin<<<WW, 256>>>(snakes, (float*)d_out);
}